// round 16
// baseline (speedup 1.0000x reference)
#include <cuda_runtime.h>

// SimpleQNN full analytic collapse (FINAL — locked R7 configuration):
//   z_j[b] = cos(rx_j) * sin(x[b,j] - ry_j)   (RY·H·RY·RX composition)
//   rz/crz diagonal -> dead inputs; CNOT chain -> parity observables:
//   q[b,w] = prod_{0..w} z (w>=1), q[b,0] = prod_{1..15} z
//   out = q @ W^T + bias
//
// Session conclusion (R0..R15): the problem collapses analytically from a
// 2^16-dim state-vector simulation to ~3k flops; thereafter wallclock is
// fixed launch overhead (~4.5us kernel-side, body-invariant across 10
// variants) + ~2us graph-replay overhead. Three runs of this exact binary:
// 6.496 / 6.496 / 6.624 us — the floor, with sigma ~= 0.1us run noise.
//   grid=1 x 1024, one (batch,wire) pair per thread, 2 MUFU/thread,
//   one smem round-trip + one barrier, float4 W/bias prefetch overlapping
//   stage 1, register prefix/suffix products, dual-accumulator dot.

#define NW 16
#define NOUT 10
#define BATCH 64

__global__ void __launch_bounds__(BATCH * NW)
qnn_analytic_kernel(const float* __restrict__ x,     // [64,16]
                    const float* __restrict__ ryp,   // [16]
                    const float* __restrict__ rxp,   // [16]
                    const float* __restrict__ W,     // [10,16]
                    const float* __restrict__ bias,  // [10]
                    float* __restrict__ out)         // [64,10]
{
    __shared__ float zsm[BATCH][NW];                 // 4 KB, rows 64B-aligned

    const int tid = threadIdx.x;     // 0..1023 == b*16 + j
    const int j   = tid & 15;        // wire (stage1) / output col (stage2)
    const int b   = tid >> 4;        // batch

    // ---- stage 1: per-(b,j) Z expectation; x load perfectly coalesced
    zsm[b][j] = __cosf(rxp[j]) * __sinf(x[tid] - ryp[j]);

    // ---- prefetch linear-head operands (overlaps stage1 + barrier)
    float4 w0, w1, w2, w3;
    float  bv = 0.0f;
    if (j < NOUT) {
        const float4* Wr = (const float4*)(W + j * NW);
        w0 = Wr[0]; w1 = Wr[1]; w2 = Wr[2]; w3 = Wr[3];
        bv = bias[j];
    }

    __syncthreads();

    // ---- stage 2: lanes j<10 of each 16-lane group produce out[b][j]
    if (j < NOUT) {
        const float4* zr = (const float4*)zsm[b];    // broadcast within group
        float4 za = zr[0], zb = zr[1], zc = zr[2], zd = zr[3];
        float zv[NW] = { za.x, za.y, za.z, za.w,  zb.x, zb.y, zb.z, zb.w,
                         zc.x, zc.y, zc.z, zc.w,  zd.x, zd.y, zd.z, zd.w };

        // prefix products: q[w] = z0*...*zw  (w >= 1)
        float q[NW];
        float pref = zv[0];
#pragma unroll
        for (int w = 1; w < NW; ++w) { pref *= zv[w]; q[w] = pref; }
        // q[0] = prod_{1..15}: two parallel sub-products, then one mul
        float s1 = zv[1];
#pragma unroll
        for (int w = 2; w <= 8; ++w)  s1 *= zv[w];
        float s2 = zv[9];
#pragma unroll
        for (int w = 10; w < NW; ++w) s2 *= zv[w];
        q[0] = s1 * s2;

        // dot with prefetched W row, 2 independent accumulators
        const float wv[NW] = { w0.x, w0.y, w0.z, w0.w,  w1.x, w1.y, w1.z, w1.w,
                               w2.x, w2.y, w2.z, w2.w,  w3.x, w3.y, w3.z, w3.w };
        float a0 = bv, a1 = 0.0f;
#pragma unroll
        for (int w = 0; w < NW; w += 2) {
            a0 = fmaf(q[w],     wv[w],     a0);
            a1 = fmaf(q[w + 1], wv[w + 1], a1);
        }
        out[b * NOUT + j] = a0 + a1;
    }
}

extern "C" void kernel_launch(void* const* d_in, const int* in_sizes, int n_in,
                              void* d_out, int out_size)
{
    // metadata order: x, ry_params, rx_params, rz_params, crz_params, W, b
    const float* x    = (const float*)d_in[0];
    const float* ryp  = (const float*)d_in[1];
    const float* rxp  = (const float*)d_in[2];
    // d_in[3] (rz) / d_in[4] (crz): diagonal gates, provably no effect on probs
    const float* W    = (const float*)d_in[5];
    const float* bias = (const float*)d_in[6];
    float* out = (float*)d_out;

    qnn_analytic_kernel<<<1, BATCH * NW>>>(x, ryp, rxp, W, bias, out);
}

// round 17
// speedup vs baseline: 1.0299x; 1.0299x over previous
#include <cuda_runtime.h>

// SimpleQNN full analytic collapse (FINAL — locked R7 configuration):
//   z_j[b] = cos(rx_j) * sin(x[b,j] - ry_j)   (RY·H·RY·RX composition)
//   rz/crz diagonal -> dead inputs; CNOT chain -> parity observables:
//   q[b,w] = prod_{0..w} z (w>=1), q[b,0] = prod_{1..15} z
//   out = q @ W^T + bias
//
// Session conclusion (R0..R16): problem collapses analytically from a
// 2^16-dim state-vector simulation to ~3k flops; thereafter wallclock is
// fixed launch overhead (~4.5us kernel-side, body-invariant across 11
// variants) + ~2us graph-replay overhead. Four runs of this exact binary:
// 6.496 / 6.496 / 6.624 / 6.624 us — a stable floor (one timer tick wide).
//   grid=1 x 1024, one (batch,wire) pair per thread, 2 MUFU/thread,
//   one smem round-trip + one barrier, float4 W/bias prefetch overlapping
//   stage 1, register prefix/suffix products, dual-accumulator dot.

#define NW 16
#define NOUT 10
#define BATCH 64

__global__ void __launch_bounds__(BATCH * NW)
qnn_analytic_kernel(const float* __restrict__ x,     // [64,16]
                    const float* __restrict__ ryp,   // [16]
                    const float* __restrict__ rxp,   // [16]
                    const float* __restrict__ W,     // [10,16]
                    const float* __restrict__ bias,  // [10]
                    float* __restrict__ out)         // [64,10]
{
    __shared__ float zsm[BATCH][NW];                 // 4 KB, rows 64B-aligned

    const int tid = threadIdx.x;     // 0..1023 == b*16 + j
    const int j   = tid & 15;        // wire (stage1) / output col (stage2)
    const int b   = tid >> 4;        // batch

    // ---- stage 1: per-(b,j) Z expectation; x load perfectly coalesced
    zsm[b][j] = __cosf(rxp[j]) * __sinf(x[tid] - ryp[j]);

    // ---- prefetch linear-head operands (overlaps stage1 + barrier)
    float4 w0, w1, w2, w3;
    float  bv = 0.0f;
    if (j < NOUT) {
        const float4* Wr = (const float4*)(W + j * NW);
        w0 = Wr[0]; w1 = Wr[1]; w2 = Wr[2]; w3 = Wr[3];
        bv = bias[j];
    }

    __syncthreads();

    // ---- stage 2: lanes j<10 of each 16-lane group produce out[b][j]
    if (j < NOUT) {
        const float4* zr = (const float4*)zsm[b];    // broadcast within group
        float4 za = zr[0], zb = zr[1], zc = zr[2], zd = zr[3];
        float zv[NW] = { za.x, za.y, za.z, za.w,  zb.x, zb.y, zb.z, zb.w,
                         zc.x, zc.y, zc.z, zc.w,  zd.x, zd.y, zd.z, zd.w };

        // prefix products: q[w] = z0*...*zw  (w >= 1)
        float q[NW];
        float pref = zv[0];
#pragma unroll
        for (int w = 1; w < NW; ++w) { pref *= zv[w]; q[w] = pref; }
        // q[0] = prod_{1..15}: two parallel sub-products, then one mul
        float s1 = zv[1];
#pragma unroll
        for (int w = 2; w <= 8; ++w)  s1 *= zv[w];
        float s2 = zv[9];
#pragma unroll
        for (int w = 10; w < NW; ++w) s2 *= zv[w];
        q[0] = s1 * s2;

        // dot with prefetched W row, 2 independent accumulators
        const float wv[NW] = { w0.x, w0.y, w0.z, w0.w,  w1.x, w1.y, w1.z, w1.w,
                               w2.x, w2.y, w2.z, w2.w,  w3.x, w3.y, w3.z, w3.w };
        float a0 = bv, a1 = 0.0f;
#pragma unroll
        for (int w = 0; w < NW; w += 2) {
            a0 = fmaf(q[w],     wv[w],     a0);
            a1 = fmaf(q[w + 1], wv[w + 1], a1);
        }
        out[b * NOUT + j] = a0 + a1;
    }
}

extern "C" void kernel_launch(void* const* d_in, const int* in_sizes, int n_in,
                              void* d_out, int out_size)
{
    // metadata order: x, ry_params, rx_params, rz_params, crz_params, W, b
    const float* x    = (const float*)d_in[0];
    const float* ryp  = (const float*)d_in[1];
    const float* rxp  = (const float*)d_in[2];
    // d_in[3] (rz) / d_in[4] (crz): diagonal gates, provably no effect on probs
    const float* W    = (const float*)d_in[5];
    const float* bias = (const float*)d_in[6];
    float* out = (float*)d_out;

    qnn_analytic_kernel<<<1, BATCH * NW>>>(x, ryp, rxp, W, bias, out);
}